// round 1
// baseline (speedup 1.0000x reference)
#include <cuda_runtime.h>
#include <cuda_bf16.h>
#include <cstdint>
#include <cstddef>

// Problem constants
#define NTOK 2048
#define DIM  2048
#define HEADS 16
#define HD 128
#define NN ((size_t)NTOK * NTOK)

// Scratch buffers (device globals: allocation-free per harness rules)
__device__ float g_Q[(size_t)NTOK * DIM];
__device__ float g_K[(size_t)NTOK * DIM];
__device__ float g_V[(size_t)NTOK * DIM];
__device__ float g_S[(size_t)HEADS * NTOK * NTOK];   // 256 MB scores
__device__ float g_O[(size_t)NTOK * DIM];
__device__ float g_H[(size_t)NTOK * DIM];
__device__ float g_E1[(size_t)NTOK * DIM];

// ---------------------------------------------------------------------------
// Register-blocked SGEMM:  C[m,n] = sum_k A[m,k] * B'[n,k]  (+bias, relu, res)
//   B_IS_KN=false: B is [N,K] row-major (i.e. C = A @ B^T)   -> QKV/FFN/scores
//   B_IS_KN=true : B is [K,N] row-major (i.e. C = A @ B)     -> O = P @ V
// Tile: BM=128, BN=128, BK=8, 256 threads, 8x8 per thread.
// blockIdx.z selects a "head" via per-operand strides aZ/bZ/cZ.
// ---------------------------------------------------------------------------
#define BM 128
#define BN 128
#define BK 8

template<bool B_IS_KN, bool BIAS, bool DO_RELU, bool RES>
__global__ __launch_bounds__(256, 2)
void gemm_k(const float* __restrict__ A, int lda, long long aZ,
            const float* __restrict__ B, int ldb, long long bZ,
            float*       __restrict__ C, int ldc, long long cZ,
            const float* __restrict__ bias,
            const float* __restrict__ res, int ldr,
            int K)
{
    A += (size_t)blockIdx.z * aZ;
    B += (size_t)blockIdx.z * bZ;
    C += (size_t)blockIdx.z * cZ;

    const int m0 = blockIdx.y * BM;
    const int n0 = blockIdx.x * BN;

    __shared__ float As[BK][BM];
    __shared__ float Bs[BK][BN];

    const int tid = threadIdx.x;
    const int tx = tid & 15;     // 0..15 -> n
    const int ty = tid >> 4;     // 0..15 -> m

    // loader indices
    const int arow = tid >> 1;          // 0..127
    const int acol = (tid & 1) * 4;     // 0 or 4
    const int brow_kn = tid >> 5;       // 0..7
    const int bcol_kn = (tid & 31) * 4; // 0..124

    float acc[8][8];
#pragma unroll
    for (int i = 0; i < 8; ++i)
#pragma unroll
        for (int j = 0; j < 8; ++j) acc[i][j] = 0.f;

    for (int k0 = 0; k0 < K; k0 += BK) {
        // A tile: [BM x BK], store transposed As[k][m]
        float4 av = *(const float4*)(A + (size_t)(m0 + arow) * lda + k0 + acol);
        As[acol + 0][arow] = av.x;
        As[acol + 1][arow] = av.y;
        As[acol + 2][arow] = av.z;
        As[acol + 3][arow] = av.w;

        if (B_IS_KN) {
            // B tile: [BK x BN] contiguous rows
            float4 bv = *(const float4*)(B + (size_t)(k0 + brow_kn) * ldb + n0 + bcol_kn);
            *(float4*)&Bs[brow_kn][bcol_kn] = bv;
        } else {
            // B tile: [BN x BK], store transposed Bs[k][n]
            float4 bv = *(const float4*)(B + (size_t)(n0 + arow) * ldb + k0 + acol);
            Bs[acol + 0][arow] = bv.x;
            Bs[acol + 1][arow] = bv.y;
            Bs[acol + 2][arow] = bv.z;
            Bs[acol + 3][arow] = bv.w;
        }
        __syncthreads();

#pragma unroll
        for (int k = 0; k < BK; ++k) {
            float a[8], b[8];
            *(float4*)(a)     = *(const float4*)&As[k][ty * 4];
            *(float4*)(a + 4) = *(const float4*)&As[k][64 + ty * 4];
            *(float4*)(b)     = *(const float4*)&Bs[k][tx * 4];
            *(float4*)(b + 4) = *(const float4*)&Bs[k][64 + tx * 4];
#pragma unroll
            for (int i = 0; i < 8; ++i)
#pragma unroll
                for (int j = 0; j < 8; ++j)
                    acc[i][j] += a[i] * b[j];
        }
        __syncthreads();
    }

    // epilogue
#pragma unroll
    for (int ih = 0; ih < 2; ++ih) {
#pragma unroll
        for (int i = 0; i < 4; ++i) {
            const int mi = m0 + ih * 64 + ty * 4 + i;
            float* crow = C + (size_t)mi * ldc;
#pragma unroll
            for (int jh = 0; jh < 2; ++jh) {
                const int nj = n0 + jh * 64 + tx * 4;
                float4 v;
                v.x = acc[ih * 4 + i][jh * 4 + 0];
                v.y = acc[ih * 4 + i][jh * 4 + 1];
                v.z = acc[ih * 4 + i][jh * 4 + 2];
                v.w = acc[ih * 4 + i][jh * 4 + 3];
                if (BIAS) {
                    const float4 bv = *(const float4*)(bias + nj);
                    v.x += bv.x; v.y += bv.y; v.z += bv.z; v.w += bv.w;
                }
                if (DO_RELU) {
                    v.x = fmaxf(v.x, 0.f); v.y = fmaxf(v.y, 0.f);
                    v.z = fmaxf(v.z, 0.f); v.w = fmaxf(v.w, 0.f);
                }
                if (RES) {
                    const float4 rv = *(const float4*)(res + (size_t)mi * ldr + nj);
                    v.x += rv.x; v.y += rv.y; v.z += rv.z; v.w += rv.w;
                }
                *(float4*)(crow + nj) = v;
            }
        }
    }
}

// ---------------------------------------------------------------------------
// Row softmax over 2048 elements, with scale applied pre-exp.
// grid = HEADS*NTOK blocks, 256 threads, 8 elems/thread.
// ---------------------------------------------------------------------------
__global__ __launch_bounds__(256)
void softmax_k(float* __restrict__ S, float scale)
{
    float* p = S + (size_t)blockIdx.x * NTOK;
    const int t = threadIdx.x;
    const int lane = t & 31, warp = t >> 5;

    float4 v0 = ((const float4*)p)[t];
    float4 v1 = ((const float4*)p)[t + 256];

    float m = fmaxf(fmaxf(fmaxf(v0.x, v0.y), fmaxf(v0.z, v0.w)),
                    fmaxf(fmaxf(v1.x, v1.y), fmaxf(v1.z, v1.w)));
#pragma unroll
    for (int o = 16; o > 0; o >>= 1) m = fmaxf(m, __shfl_xor_sync(0xffffffffu, m, o));

    __shared__ float red[8];
    if (lane == 0) red[warp] = m;
    __syncthreads();
    float M = red[0];
#pragma unroll
    for (int w = 1; w < 8; ++w) M = fmaxf(M, red[w]);

    v0.x = __expf((v0.x - M) * scale); v0.y = __expf((v0.y - M) * scale);
    v0.z = __expf((v0.z - M) * scale); v0.w = __expf((v0.w - M) * scale);
    v1.x = __expf((v1.x - M) * scale); v1.y = __expf((v1.y - M) * scale);
    v1.z = __expf((v1.z - M) * scale); v1.w = __expf((v1.w - M) * scale);

    float s = v0.x + v0.y + v0.z + v0.w + v1.x + v1.y + v1.z + v1.w;
#pragma unroll
    for (int o = 16; o > 0; o >>= 1) s += __shfl_xor_sync(0xffffffffu, s, o);
    __syncthreads();   // reuse red[]
    if (lane == 0) red[warp] = s;
    __syncthreads();
    float Ssum = 0.f;
#pragma unroll
    for (int w = 0; w < 8; ++w) Ssum += red[w];
    const float inv = 1.0f / Ssum;

    v0.x *= inv; v0.y *= inv; v0.z *= inv; v0.w *= inv;
    v1.x *= inv; v1.y *= inv; v1.z *= inv; v1.w *= inv;
    ((float4*)p)[t] = v0;
    ((float4*)p)[t + 256] = v1;
}

// ---------------------------------------------------------------------------
// Host launch
// ---------------------------------------------------------------------------
extern "C" void kernel_launch(void* const* d_in, const int* in_sizes, int n_in,
                              void* d_out, int out_size)
{
    (void)in_sizes; (void)n_in; (void)out_size;
    const float* E  = (const float*)d_in[0];
    const float* Wq = (const float*)d_in[1];
    const float* bq = (const float*)d_in[2];
    const float* Wk = (const float*)d_in[3];
    const float* bk = (const float*)d_in[4];
    const float* Wv = (const float*)d_in[5];
    const float* bv = (const float*)d_in[6];
    const float* W0 = (const float*)d_in[7];
    const float* b0 = (const float*)d_in[8];
    const float* W1 = (const float*)d_in[9];
    const float* b1 = (const float*)d_in[10];

    float *Q, *K, *V, *S, *O, *H, *E1;
    cudaGetSymbolAddress((void**)&Q,  g_Q);
    cudaGetSymbolAddress((void**)&K,  g_K);
    cudaGetSymbolAddress((void**)&V,  g_V);
    cudaGetSymbolAddress((void**)&S,  g_S);
    cudaGetSymbolAddress((void**)&O,  g_O);
    cudaGetSymbolAddress((void**)&H,  g_H);
    cudaGetSymbolAddress((void**)&E1, g_E1);

    const dim3 blk(256);
    const dim3 grid_full(DIM / BN, NTOK / BM, 1);      // 16x16
    const dim3 grid_sc(NTOK / BN, NTOK / BM, HEADS);   // 16x16x16
    const dim3 grid_ov(1, NTOK / BM, HEADS);           // 1x16x16
    const float scale = 0.08838834764831845f;          // 1/sqrt(128)

    for (int r = 0; r < 2; ++r) {
        const float* Ein  = (r == 0) ? E : E1;
        float*       Eout = (r == 0) ? E1 : (float*)d_out;

        // QKV projections: X = Ein @ W^T + b
        gemm_k<false, true, false, false><<<grid_full, blk>>>(
            Ein, DIM, 0, Wq, DIM, 0, Q, DIM, 0, bq, nullptr, 0, DIM);
        gemm_k<false, true, false, false><<<grid_full, blk>>>(
            Ein, DIM, 0, Wk, DIM, 0, K, DIM, 0, bk, nullptr, 0, DIM);
        gemm_k<false, true, false, false><<<grid_full, blk>>>(
            Ein, DIM, 0, Wv, DIM, 0, V, DIM, 0, bv, nullptr, 0, DIM);

        // Scores per head: S_h = Q_h @ K_h^T   (M=N=2048, K=128)
        gemm_k<false, false, false, false><<<grid_sc, blk>>>(
            Q, DIM, HD, K, DIM, HD, S, NTOK, (long long)NN,
            nullptr, nullptr, 0, HD);

        // Softmax with scale
        softmax_k<<<HEADS * NTOK, blk>>>(S, scale);

        // O_h = P_h @ V_h   (M=2048, N=128, K=2048; B is [K,N])
        gemm_k<true, false, false, false><<<grid_ov, blk>>>(
            S, NTOK, (long long)NN, V, DIM, HD, O, DIM, HD,
            nullptr, nullptr, 0, NTOK);

        // H = relu(O @ W0^T + b0)
        gemm_k<false, true, true, false><<<grid_full, blk>>>(
            O, DIM, 0, W0, DIM, 0, H, DIM, 0, b0, nullptr, 0, DIM);

        // Eout = Ein + relu(H @ W1^T + b1)
        gemm_k<false, true, true, true><<<grid_full, blk>>>(
            H, DIM, 0, W1, DIM, 0, Eout, DIM, 0, b1, Ein, DIM, DIM);
    }
}

// round 3
// speedup vs baseline: 1.5812x; 1.5812x over previous
#include <cuda_runtime.h>
#include <cuda_bf16.h>
#include <cstdint>
#include <cstddef>

// Problem constants
#define NTOK 2048
#define DIM  2048
#define HEADS 16
#define HD 128
#define NN ((size_t)NTOK * NTOK)

// Scratch buffers (device globals: allocation-free per harness rules)
__device__ float g_Q[(size_t)NTOK * DIM];
__device__ float g_K[(size_t)NTOK * DIM];
__device__ float g_V[(size_t)NTOK * DIM];
__device__ float g_S[(size_t)HEADS * NTOK * NTOK];   // 256 MB scores
__device__ float g_O[(size_t)NTOK * DIM];
__device__ float g_H[(size_t)NTOK * DIM];
__device__ float g_E1[(size_t)NTOK * DIM];

// ---------------------------------------------------------------------------
// TF32 tensor-core GEMM:  C[m,n] = sum_k A[m,k] * B'[n,k]  (+bias, relu, res)
//   B_IS_KN=false: B is [N,K] row-major (C = A @ B^T)  -> QKV / scores / FFN
//   B_IS_KN=true : B is [K,N] row-major (C = A @ B)    -> O = P @ V
// CTA tile 128x128x16, 8 warps (4x2), warp tile 32x64 of m16n8k8 mma.
// Operands staged in SMEM in fragment-permuted layout -> conflict-free
// vectorized fragment loads.
// ---------------------------------------------------------------------------
#define BM 128
#define BN 128
#define BK 16

__device__ __forceinline__ float to_tf32(float x) {
    uint32_t u;
    asm("cvt.rna.tf32.f32 %0, %1;" : "=r"(u) : "f"(x));
    return __uint_as_float(u);
}

__device__ __forceinline__ void mma_tf32(float* c, const uint4& a, const uint2& b) {
    asm volatile(
        "mma.sync.aligned.m16n8k8.row.col.f32.tf32.tf32.f32 "
        "{%0,%1,%2,%3}, {%4,%5,%6,%7}, {%8,%9}, {%0,%1,%2,%3};"
        : "+f"(c[0]), "+f"(c[1]), "+f"(c[2]), "+f"(c[3])
        : "r"(a.x), "r"(a.y), "r"(a.z), "r"(a.w), "r"(b.x), "r"(b.y));
}

template<bool B_IS_KN, bool BIAS, bool DO_RELU, bool RES>
__global__ __launch_bounds__(256)
void gemm_tc(const float* __restrict__ A, int lda, long long aZ,
             const float* __restrict__ B, int ldb, long long bZ,
             float*       __restrict__ C, int ldc, long long cZ,
             const float* __restrict__ bias,
             const float* __restrict__ res, int ldr,
             int K)
{
    A += (size_t)blockIdx.z * aZ;
    B += (size_t)blockIdx.z * bZ;
    C += (size_t)blockIdx.z * cZ;

    const int m0 = blockIdx.y * BM;
    const int n0 = blockIdx.x * BN;

    // Fragment-permuted staging:
    //  As[((ks*8  + mtile)*32 + lane)*4 + f]   (ks:0..1, mtile:0..7, f = a0..a3)
    //  Bs[((ks*16 + ntile)*32 + lane)*2 + h]   (ntile:0..15, h = b0..b1)
    __shared__ float As[2 * 8 * 32 * 4];
    __shared__ float Bs[2 * 16 * 32 * 2];

    const int tid  = threadIdx.x;
    const int lane = tid & 31;
    const int warp = tid >> 5;
    const int wm = warp & 3;     // 0..3 -> 32-row slab
    const int wn = warp >> 2;    // 0..1 -> 64-col slab

    float acc[2][8][4];
#pragma unroll
    for (int mt = 0; mt < 2; ++mt)
#pragma unroll
        for (int nt = 0; nt < 8; ++nt)
#pragma unroll
            for (int f = 0; f < 4; ++f) acc[mt][nt][f] = 0.f;

    for (int k0 = 0; k0 < K; k0 += BK) {
        // ---- stage A [BM x BK] ----
#pragma unroll
        for (int i = 0; i < 2; ++i) {
            const int r  = (tid >> 2) + i * 64;       // 0..127
            const int c4 = (tid & 3) * 4;             // 0,4,8,12
            const float4 v = *(const float4*)(A + (size_t)(m0 + r) * lda + k0 + c4);
            const int mt = r >> 4, mm = r & 15;
            const int g = mm & 7, rh = mm >> 3;
            const int ks = c4 >> 3, ch = (c4 >> 2) & 1;
            float* dst = As + ((ks * 8 + mt) * 32 + g * 4) * 4 + (rh + 2 * ch);
            dst[0]  = to_tf32(v.x);
            dst[4]  = to_tf32(v.y);
            dst[8]  = to_tf32(v.z);
            dst[12] = to_tf32(v.w);
        }
        // ---- stage B ----
        if (B_IS_KN) {
            // B[K][N] tile [BK x BN]
#pragma unroll
            for (int i = 0; i < 2; ++i) {
                const int kr = (tid >> 5) + i * 8;    // 0..15
                const int c  = (tid & 31) * 4;        // 0..124
                const float4 v = *(const float4*)(B + (size_t)(k0 + kr) * ldb + n0 + c);
                const int ks = kr >> 3, tq = kr & 3, h = (kr >> 2) & 1;
                const int ntl = c >> 3, gb = c & 7;   // gb in {0,4}
                float* dst = Bs + ((ks * 16 + ntl) * 32 + gb * 4 + tq) * 2 + h;
                dst[0]  = to_tf32(v.x);
                dst[8]  = to_tf32(v.y);
                dst[16] = to_tf32(v.z);
                dst[24] = to_tf32(v.w);
            }
        } else {
            // B[N][K] tile [BN x BK]
#pragma unroll
            for (int i = 0; i < 2; ++i) {
                const int r  = (tid >> 2) + i * 64;   // 0..127 (n)
                const int c4 = (tid & 3) * 4;
                const float4 v = *(const float4*)(B + (size_t)(n0 + r) * ldb + k0 + c4);
                const int ntl = r >> 3, g = r & 7;
                const int ks = c4 >> 3, h = (c4 >> 2) & 1;
                float* dst = Bs + ((ks * 16 + ntl) * 32 + g * 4) * 2 + h;
                dst[0] = to_tf32(v.x);
                dst[2] = to_tf32(v.y);
                dst[4] = to_tf32(v.z);
                dst[6] = to_tf32(v.w);
            }
        }
        __syncthreads();

        // ---- compute: 2 k-steps of 8 ----
#pragma unroll
        for (int ks = 0; ks < 2; ++ks) {
            uint4 afr[2];
#pragma unroll
            for (int mt = 0; mt < 2; ++mt)
                afr[mt] = *(const uint4*)(As + ((ks * 8 + wm * 2 + mt) * 32 + lane) * 4);
            uint2 bfr[8];
#pragma unroll
            for (int nt = 0; nt < 8; ++nt)
                bfr[nt] = *(const uint2*)(Bs + ((ks * 16 + wn * 8 + nt) * 32 + lane) * 2);
#pragma unroll
            for (int mt = 0; mt < 2; ++mt)
#pragma unroll
                for (int nt = 0; nt < 8; ++nt)
                    mma_tf32(acc[mt][nt], afr[mt], bfr[nt]);
        }
        __syncthreads();
    }

    // ---- epilogue ----
    const int g  = lane >> 2;
    const int tq = lane & 3;
#pragma unroll
    for (int mt = 0; mt < 2; ++mt) {
        const int row0 = m0 + wm * 32 + mt * 16 + g;
#pragma unroll
        for (int nt = 0; nt < 8; ++nt) {
            const int col = n0 + wn * 64 + nt * 8 + tq * 2;
            float2 v0 = make_float2(acc[mt][nt][0], acc[mt][nt][1]);
            float2 v1 = make_float2(acc[mt][nt][2], acc[mt][nt][3]);
            if (BIAS) {
                const float2 bv = *(const float2*)(bias + col);
                v0.x += bv.x; v0.y += bv.y;
                v1.x += bv.x; v1.y += bv.y;
            }
            if (DO_RELU) {
                v0.x = fmaxf(v0.x, 0.f); v0.y = fmaxf(v0.y, 0.f);
                v1.x = fmaxf(v1.x, 0.f); v1.y = fmaxf(v1.y, 0.f);
            }
            if (RES) {
                const float2 r0 = *(const float2*)(res + (size_t)row0 * ldr + col);
                const float2 r1 = *(const float2*)(res + (size_t)(row0 + 8) * ldr + col);
                v0.x += r0.x; v0.y += r0.y;
                v1.x += r1.x; v1.y += r1.y;
            }
            *(float2*)(C + (size_t)row0 * ldc + col) = v0;
            *(float2*)(C + (size_t)(row0 + 8) * ldc + col) = v1;
        }
    }
}

// ---------------------------------------------------------------------------
// Row softmax over 2048 elements, with scale applied pre-exp.
// ---------------------------------------------------------------------------
__global__ __launch_bounds__(256)
void softmax_k(float* __restrict__ S, float scale)
{
    float* p = S + (size_t)blockIdx.x * NTOK;
    const int t = threadIdx.x;
    const int lane = t & 31, warp = t >> 5;

    float4 v0 = ((const float4*)p)[t];
    float4 v1 = ((const float4*)p)[t + 256];

    float m = fmaxf(fmaxf(fmaxf(v0.x, v0.y), fmaxf(v0.z, v0.w)),
                    fmaxf(fmaxf(v1.x, v1.y), fmaxf(v1.z, v1.w)));
#pragma unroll
    for (int o = 16; o > 0; o >>= 1) m = fmaxf(m, __shfl_xor_sync(0xffffffffu, m, o));

    __shared__ float red[8];
    if (lane == 0) red[warp] = m;
    __syncthreads();
    float M = red[0];
#pragma unroll
    for (int w = 1; w < 8; ++w) M = fmaxf(M, red[w]);

    v0.x = __expf((v0.x - M) * scale); v0.y = __expf((v0.y - M) * scale);
    v0.z = __expf((v0.z - M) * scale); v0.w = __expf((v0.w - M) * scale);
    v1.x = __expf((v1.x - M) * scale); v1.y = __expf((v1.y - M) * scale);
    v1.z = __expf((v1.z - M) * scale); v1.w = __expf((v1.w - M) * scale);

    float s = v0.x + v0.y + v0.z + v0.w + v1.x + v1.y + v1.z + v1.w;
#pragma unroll
    for (int o = 16; o > 0; o >>= 1) s += __shfl_xor_sync(0xffffffffu, s, o);
    __syncthreads();
    if (lane == 0) red[warp] = s;
    __syncthreads();
    float Ssum = 0.f;
#pragma unroll
    for (int w = 0; w < 8; ++w) Ssum += red[w];
    const float inv = 1.0f / Ssum;

    v0.x *= inv; v0.y *= inv; v0.z *= inv; v0.w *= inv;
    v1.x *= inv; v1.y *= inv; v1.z *= inv; v1.w *= inv;
    ((float4*)p)[t] = v0;
    ((float4*)p)[t + 256] = v1;
}

// ---------------------------------------------------------------------------
// Host launch
// ---------------------------------------------------------------------------
extern "C" void kernel_launch(void* const* d_in, const int* in_sizes, int n_in,
                              void* d_out, int out_size)
{
    (void)in_sizes; (void)n_in; (void)out_size;
    const float* E  = (const float*)d_in[0];
    const float* Wq = (const float*)d_in[1];
    const float* bq = (const float*)d_in[2];
    const float* Wk = (const float*)d_in[3];
    const float* bk = (const float*)d_in[4];
    const float* Wv = (const float*)d_in[5];
    const float* bv = (const float*)d_in[6];
    const float* W0 = (const float*)d_in[7];
    const float* b0 = (const float*)d_in[8];
    const float* W1 = (const float*)d_in[9];
    const float* b1 = (const float*)d_in[10];

    float *Q, *K, *V, *S, *O, *H, *E1;
    cudaGetSymbolAddress((void**)&Q,  g_Q);
    cudaGetSymbolAddress((void**)&K,  g_K);
    cudaGetSymbolAddress((void**)&V,  g_V);
    cudaGetSymbolAddress((void**)&S,  g_S);
    cudaGetSymbolAddress((void**)&O,  g_O);
    cudaGetSymbolAddress((void**)&H,  g_H);
    cudaGetSymbolAddress((void**)&E1, g_E1);

    const dim3 blk(256);
    const dim3 grid_full(DIM / BN, NTOK / BM, 1);      // 16x16
    const dim3 grid_sc(NTOK / BN, NTOK / BM, HEADS);   // 16x16x16
    const dim3 grid_ov(1, NTOK / BM, HEADS);           // 1x16x16
    const float scale = 0.08838834764831845f;          // 1/sqrt(128)

    for (int r = 0; r < 2; ++r) {
        const float* Ein  = (r == 0) ? E : E1;
        float*       Eout = (r == 0) ? E1 : (float*)d_out;

        // QKV projections: X = Ein @ W^T + b
        gemm_tc<false, true, false, false><<<grid_full, blk>>>(
            Ein, DIM, 0, Wq, DIM, 0, Q, DIM, 0, bq, nullptr, 0, DIM);
        gemm_tc<false, true, false, false><<<grid_full, blk>>>(
            Ein, DIM, 0, Wk, DIM, 0, K, DIM, 0, bk, nullptr, 0, DIM);
        gemm_tc<false, true, false, false><<<grid_full, blk>>>(
            Ein, DIM, 0, Wv, DIM, 0, V, DIM, 0, bv, nullptr, 0, DIM);

        // Scores per head: S_h = Q_h @ K_h^T   (M=N=2048, K=128)
        gemm_tc<false, false, false, false><<<grid_sc, blk>>>(
            Q, DIM, HD, K, DIM, HD, S, NTOK, (long long)NN,
            nullptr, nullptr, 0, HD);

        // Softmax with scale
        softmax_k<<<HEADS * NTOK, blk>>>(S, scale);

        // O_h = P_h @ V_h   (M=2048, N=128, K=2048; B is [K,N])
        gemm_tc<true, false, false, false><<<grid_ov, blk>>>(
            S, NTOK, (long long)NN, V, DIM, HD, O, DIM, HD,
            nullptr, nullptr, 0, NTOK);

        // H = relu(O @ W0^T + b0)
        gemm_tc<false, true, true, false><<<grid_full, blk>>>(
            O, DIM, 0, W0, DIM, 0, H, DIM, 0, b0, nullptr, 0, DIM);

        // Eout = Ein + relu(H @ W1^T + b1)
        gemm_tc<false, true, true, true><<<grid_full, blk>>>(
            H, DIM, 0, W1, DIM, 0, Eout, DIM, 0, b1, Ein, DIM, DIM);
    }
}